// round 2
// baseline (speedup 1.0000x reference)
#include <cuda_runtime.h>
#include <cstdint>
#include <cstddef>

#define T_TOK 16384
#define H_DIM 2048
#define N_EXP 64
#define TOPK  8

// ---------------- scratch (no allocations allowed) ----------------
__device__ float g_topw[T_TOK * TOPK];
__device__ int   g_topidx[T_TOK * TOPK];
__device__ float g_sumw[T_TOK];

// ---------------- helpers ----------------
__device__ __forceinline__ void fma2(unsigned long long &d,
                                     unsigned long long a,
                                     unsigned long long b) {
    // {d.lo,d.hi} += {a.lo,a.hi} * {b.lo,b.hi}   (packed f32x2 FMA, sm_100+)
    asm volatile("fma.rn.f32x2 %0, %1, %2, %0;" : "+l"(d) : "l"(a), "l"(b));
}

__device__ __forceinline__ void cp_async16(uint32_t saddr, const void* gptr) {
    asm volatile("cp.async.cg.shared.global [%0], [%1], 16;" :: "r"(saddr), "l"(gptr));
}
__device__ __forceinline__ void cp_commit() { asm volatile("cp.async.commit_group;"); }
__device__ __forceinline__ void cp_wait1()  { asm volatile("cp.async.wait_group 1;"); }
__device__ __forceinline__ void cp_wait0()  { asm volatile("cp.async.wait_group 0;"); }

// ================= Kernel A: router GEMM + softmax + top-8 =================
// Grid: T/64 CTAs, 128 threads. Each CTA: 64 tokens x 64 experts.
// f32x2 pairing is along H: each accumulator holds two partial sums (even/odd h).
static constexpr int TB      = 64;            // tokens per CTA
static constexpr int HC      = 32;            // h-chunk (floats)
static constexpr int STRIDE  = HC + 4;        // 36 floats = 144B: 16B-aligned rows (cp.async.128 dst)
static constexpr int BUF_F   = (TB + N_EXP) * STRIDE;   // 4608 floats per buffer
static constexpr int NCH     = H_DIM / HC;    // 64 chunks
static constexpr int LSTRIDE = 67;            // slog row stride (conflict-free)

__global__ __launch_bounds__(128)
void router_kernel(const float* __restrict__ X,
                   const float* __restrict__ RW,
                   const float* __restrict__ RB)
{
    __shared__ __align__(16) float pool[2 * BUF_F];   // 36.9 KB, double buffer
    float* slog = pool;                               // reused after mainloop (4288 floats)

    const int tid = threadIdx.x;
    const int tb  = blockIdx.x * TB;
    const int tyg = tid >> 3;   // 0..15 : token group (4 tokens each)
    const int txg = tid & 7;    // 0..7  : expert lane (owns e = txg + 8j)

    unsigned long long acc[4][8];
    #pragma unroll
    for (int i = 0; i < 4; i++)
        #pragma unroll
        for (int j = 0; j < 8; j++) acc[i][j] = 0ull;

    // -------- staging: direct (untransposed) copies, cp.async 16B --------
    auto stage = [&](int ch, int b) {
        const int h0 = ch * HC;
        float* xs = pool + b * BUF_F;
        float* ws = xs + TB * STRIDE;
        uint32_t xs_s = (uint32_t)__cvta_generic_to_shared(xs);
        uint32_t ws_s = (uint32_t)__cvta_generic_to_shared(ws);
        #pragma unroll
        for (int r = 0; r < 4; r++) {
            int idx = tid + r * 128;        // 0..511
            int t = idx >> 3, c = idx & 7;  // t: token/expert row, c: float4 col
            cp_async16(xs_s + (uint32_t)(t * STRIDE + c * 4) * 4u,
                       &X[(size_t)(tb + t) * H_DIM + h0 + c * 4]);
            cp_async16(ws_s + (uint32_t)(t * STRIDE + c * 4) * 4u,
                       &RW[(size_t)t * H_DIM + h0 + c * 4]);
        }
        cp_commit();
    };

    stage(0, 0);
    for (int ch = 0; ch < NCH; ch++) {
        __syncthreads();                    // buffer (ch+1)&1 free for refill
        if (ch + 1 < NCH) { stage(ch + 1, (ch + 1) & 1); cp_wait1(); }
        else              { cp_wait0(); }
        __syncthreads();                    // chunk ch visible to all threads

        const float* xs = pool + (ch & 1) * BUF_F;
        const float* ws = xs + TB * STRIDE;
        #pragma unroll
        for (int hp = 0; hp < HC / 2; hp++) {
            unsigned long long xv[4];
            #pragma unroll
            for (int i = 0; i < 4; i++)
                xv[i] = *(const unsigned long long*)&xs[(tyg * 4 + i) * STRIDE + 2 * hp];
            #pragma unroll
            for (int j = 0; j < 8; j++) {
                unsigned long long wv =
                    *(const unsigned long long*)&ws[(txg + 8 * j) * STRIDE + 2 * hp];
                #pragma unroll
                for (int i = 0; i < 4; i++) fma2(acc[i][j], xv[i], wv);
            }
        }
    }

    __syncthreads();   // all compute done; slog aliases buffer 0 (disjoint from buf1)

    // -------- write logits (fold the two f32x2 partials, add router bias) --------
    #pragma unroll
    for (int i = 0; i < 4; i++) {
        #pragma unroll
        for (int j = 0; j < 8; j++) {
            unsigned lo32 = (unsigned)(acc[i][j] & 0xffffffffull);
            unsigned hi32 = (unsigned)(acc[i][j] >> 32);
            int e = txg + 8 * j;
            slog[(tyg * 4 + i) * LSTRIDE + e] =
                __uint_as_float(lo32) + __uint_as_float(hi32) + RB[e];
        }
    }
    __syncthreads();

    // -------- per-token softmax + top-8 (threads 0..63) --------
    if (tid < TB) {
        const int t = tb + tid;
        float* row = &slog[tid * LSTRIDE];
        float mx = -1e30f;
        #pragma unroll
        for (int e = 0; e < N_EXP; e++) mx = fmaxf(mx, row[e]);
        float sum = 0.f;
        #pragma unroll
        for (int e = 0; e < N_EXP; e++) {
            float p = __expf(row[e] - mx);
            row[e] = p;
            sum += p;
        }
        const float inv = 1.0f / sum;
        unsigned long long mask = 0ull;
        float sw = 0.f;
        #pragma unroll
        for (int k = 0; k < TOPK; k++) {
            float best = -1.f; int bi = 0;
            for (int e = 0; e < N_EXP; e++) {
                float v = row[e];
                bool ok = !((mask >> e) & 1ull) && (v > best);
                if (ok) { best = v; bi = e; }
            }
            mask |= 1ull << bi;
            float w = best * inv;
            g_topw[t * TOPK + k]   = w;
            g_topidx[t * TOPK + k] = bi;
            sw += w;
        }
        g_sumw[t] = sw;
    }
}

// ================= Kernel B: dispatch/combine =================
// out[t][h] = x[t][h]*sumw[t] + sum_k w_k * bias[idx_k][h]
// CTA: 128 tokens x 128 h-columns; all 64 expert bias slices staged in smem.
static constexpr int TBB = 128;   // tokens per CTA
static constexpr int HCB = 128;   // h-columns per CTA

__global__ __launch_bounds__(256)
void combine_kernel(const float* __restrict__ X,
                    const float* __restrict__ EB,
                    float* __restrict__ OUT)
{
    __shared__ __align__(16) float bs[N_EXP * HCB];   // 32 KB bias slice
    __shared__ float s_w[TBB * TOPK];
    __shared__ int   s_i[TBB * TOPK];
    __shared__ float s_s[TBB];

    const int tid = threadIdx.x;
    const int hb  = blockIdx.x * HCB;
    const int tb0 = blockIdx.y * TBB;

    // stage bias slice: 64 experts x 128 floats
    #pragma unroll
    for (int r = 0; r < 8; r++) {
        int idx = tid + r * 256;          // 0..2047 float4 slots
        int e = idx >> 5, c = idx & 31;
        *(float4*)&bs[e * HCB + c * 4] =
            *(const float4*)&EB[(size_t)e * H_DIM + hb + c * 4];
    }
    // stage token metadata
    #pragma unroll
    for (int r = 0; r < 4; r++) {
        int idx = tid + r * 256;          // 0..1023
        s_w[idx] = g_topw[tb0 * TOPK + idx];
        s_i[idx] = g_topidx[tb0 * TOPK + idx];
    }
    if (tid < TBB) s_s[tid] = g_sumw[tb0 + tid];
    __syncthreads();

    const int tl = tid >> 5;   // 0..7 token lane (one warp per token at a time)
    const int c  = tid & 31;   // float4 column

    float4 xv = *(const float4*)&X[(size_t)(tb0 + tl) * H_DIM + hb + c * 4];
    #pragma unroll 4
    for (int it = 0; it < TBB / 8; it++) {
        const int tt = tl + it * 8;
        float4 xn = xv;
        if (it + 1 < TBB / 8)
            xn = *(const float4*)&X[(size_t)(tb0 + tt + 8) * H_DIM + hb + c * 4];

        const float sw = s_s[tt];
        float4 a;
        a.x = xv.x * sw; a.y = xv.y * sw; a.z = xv.z * sw; a.w = xv.w * sw;
        #pragma unroll
        for (int k = 0; k < TOPK; k++) {
            const float wk = s_w[tt * TOPK + k];
            const int   ek = s_i[tt * TOPK + k];
            const float4 bv = *(const float4*)&bs[ek * HCB + c * 4];
            a.x += wk * bv.x; a.y += wk * bv.y; a.z += wk * bv.z; a.w += wk * bv.w;
        }
        *(float4*)&OUT[(size_t)(tb0 + tt) * H_DIM + hb + c * 4] = a;
        xv = xn;
    }
}

// ================= launch =================
extern "C" void kernel_launch(void* const* d_in, const int* in_sizes, int n_in,
                              void* d_out, int out_size) {
    const float* X  = (const float*)d_in[0];   // hidden_states [4,4096,2048]
    const float* RW = (const float*)d_in[1];   // router_weight [64,2048]
    const float* RB = (const float*)d_in[2];   // router_bias   [64]
    const float* EB = (const float*)d_in[3];   // expert_bias   [64,2048]
    float* OUT = (float*)d_out;

    router_kernel<<<T_TOK / TB, 128>>>(X, RW, RB);
    dim3 gb(H_DIM / HCB, T_TOK / TBB);
    combine_kernel<<<gb, 256>>>(X, EB, OUT);
}

// round 4
// speedup vs baseline: 1.3850x; 1.3850x over previous
#include <cuda_runtime.h>
#include <cuda_bf16.h>
#include <cstdint>
#include <cstddef>

#define T_TOK 16384
#define H_DIM 2048
#define N_EXP 64
#define TOPK  8

// ---------------- scratch (no allocations allowed) ----------------
__device__ float g_topw[T_TOK * TOPK];
__device__ int   g_topidx[T_TOK * TOPK];
__device__ float g_sumw[T_TOK];
__device__ __nv_bfloat16 g_whi[N_EXP * H_DIM];
__device__ __nv_bfloat16 g_wlo[N_EXP * H_DIM];

// ---------------- helpers ----------------
__device__ __forceinline__ void cp_async16(uint32_t saddr, const void* gptr) {
    asm volatile("cp.async.cg.shared.global [%0], [%1], 16;" :: "r"(saddr), "l"(gptr));
}
__device__ __forceinline__ void cp_commit() { asm volatile("cp.async.commit_group;"); }
__device__ __forceinline__ void cp_wait1()  { asm volatile("cp.async.wait_group 1;"); }
__device__ __forceinline__ void cp_wait0()  { asm volatile("cp.async.wait_group 0;"); }

__device__ __forceinline__ void ldsm4(uint32_t& r0, uint32_t& r1, uint32_t& r2, uint32_t& r3,
                                      uint32_t addr) {
    asm volatile("ldmatrix.sync.aligned.m8n8.x4.shared.b16 {%0,%1,%2,%3}, [%4];"
                 : "=r"(r0), "=r"(r1), "=r"(r2), "=r"(r3) : "r"(addr));
}
__device__ __forceinline__ void mma_bf16(float* d, const uint32_t* a, uint32_t b0, uint32_t b1) {
    asm volatile("mma.sync.aligned.m16n8k16.row.col.f32.bf16.bf16.f32 "
                 "{%0,%1,%2,%3},{%4,%5,%6,%7},{%8,%9},{%0,%1,%2,%3};"
                 : "+f"(d[0]), "+f"(d[1]), "+f"(d[2]), "+f"(d[3])
                 : "r"(a[0]), "r"(a[1]), "r"(a[2]), "r"(a[3]), "r"(b0), "r"(b1));
}

// ================= Kernel W-convert: RW fp32 -> bf16 hi/lo =================
__global__ __launch_bounds__(256)
void wconvert_kernel(const float* __restrict__ RW) {
    int idx = blockIdx.x * 256 + threadIdx.x;
    const int N = N_EXP * H_DIM;
    for (int i = idx; i < N; i += gridDim.x * 256) {
        float x = RW[i];
        __nv_bfloat16 hi = __float2bfloat16(x);
        g_whi[i] = hi;
        g_wlo[i] = __float2bfloat16(x - __bfloat162float(hi));
    }
}

// ================= Kernel A: HMMA router (bf16 hi/lo x3) =================
// CTA: 256 threads (8 warps), 128 tokens x 64 experts, K in 32 chunks of 64.
// Split-K: warps 0-3 handle k-steps 0-1 of each chunk, warps 4-7 steps 2-3.
// Each warp: 32 tokens (2 m16 tiles) x 64 experts (8 n8 tiles).
static constexpr int TOKB = 128;
static constexpr int KC   = 64;
static constexpr int NCH  = H_DIM / KC;   // 32

static constexpr int OFF_X  = 0;          // 2 x 32768 fp32 X (swizzled 16B chunks)
static constexpr int OFF_A  = 65536;      // Ahi 16384 + Alo 16384 (single buffer)
static constexpr int OFF_W  = 98304;      // 2 x (Whi 8192 + Wlo 8192)
static constexpr int OFF_RB = 131072;     // 256 B
static constexpr int SMEM_R = 131584;

__global__ __launch_bounds__(256, 1)
void router_mma_kernel(const float* __restrict__ X,
                       const float* __restrict__ RB)
{
    extern __shared__ __align__(16) char dsm[];
    const uint32_t sb = (uint32_t)__cvta_generic_to_shared(dsm);
    const int tid  = threadIdx.x;
    const int lane = tid & 31;
    const int wid  = tid >> 5;
    const int tb   = blockIdx.x * TOKB;
    const int kg   = wid >> 2;   // k-group: 0 -> ks 0,1 ; 1 -> ks 2,3
    const int mp   = wid & 3;    // token part: tokens [mp*32, mp*32+32)

    if (tid < N_EXP) ((float*)(dsm + OFF_RB))[tid] = RB[tid];

    auto stageX = [&](int c, int b) {
        uint32_t dst = sb + OFF_X + b * 32768;
        const float* src = X + (size_t)tb * H_DIM + c * KC;
        #pragma unroll
        for (int r = 0; r < 8; r++) {
            int idx = tid + r * 256;            // 0..2047 16B chunks
            int row = idx >> 4, c16 = idx & 15;
            cp_async16(dst + (uint32_t)(row * 256 + ((c16 ^ (row & 7)) << 4)),
                       src + (size_t)row * H_DIM + c16 * 4);
        }
    };
    auto stageW = [&](int c, int b) {
        uint32_t wh = sb + OFF_W + b * 16384;
        const __nv_bfloat16* sh = g_whi + c * KC;
        const __nv_bfloat16* sl = g_wlo + c * KC;
        #pragma unroll
        for (int r = 0; r < 2; r++) {
            int idx = tid + r * 256;            // 0..511 16B chunks
            int row = idx >> 3, c16 = idx & 7;
            uint32_t so = (uint32_t)(row * 128 + ((c16 ^ (row & 7)) << 4));
            cp_async16(wh + so,        sh + (size_t)row * H_DIM + c16 * 8);
            cp_async16(wh + 8192 + so, sl + (size_t)row * H_DIM + c16 * 8);
        }
    };
    auto convert = [&](int b) {
        uint32_t xrow = sb + OFF_X + b * 32768 + (tid & 127) * 256;
        const int row = tid & 127;
        const int half = tid >> 7;
        const int rx = row & 7;
        uint32_t ah = sb + OFF_A + row * 128;
        uint32_t al = ah + 16384;
        #pragma unroll
        for (int i = 0; i < 8; i++) {
            int c16 = half * 8 + i;
            float4 f;
            asm volatile("ld.shared.v4.f32 {%0,%1,%2,%3}, [%4];"
                         : "=f"(f.x), "=f"(f.y), "=f"(f.z), "=f"(f.w)
                         : "r"(xrow + (uint32_t)((c16 ^ rx) << 4)));
            uint32_t h01, h23, l01, l23;
            asm("cvt.rn.bf16x2.f32 %0, %1, %2;" : "=r"(h01) : "f"(f.y), "f"(f.x));
            asm("cvt.rn.bf16x2.f32 %0, %1, %2;" : "=r"(h23) : "f"(f.w), "f"(f.z));
            float e0 = f.x - __uint_as_float(h01 << 16);
            float e1 = f.y - __uint_as_float(h01 & 0xffff0000u);
            float e2 = f.z - __uint_as_float(h23 << 16);
            float e3 = f.w - __uint_as_float(h23 & 0xffff0000u);
            asm("cvt.rn.bf16x2.f32 %0, %1, %2;" : "=r"(l01) : "f"(e1), "f"(e0));
            asm("cvt.rn.bf16x2.f32 %0, %1, %2;" : "=r"(l23) : "f"(e3), "f"(e2));
            uint32_t off = (uint32_t)((((c16 >> 1) ^ rx) << 4) + (c16 & 1) * 8);
            asm volatile("st.shared.v2.b32 [%0], {%1,%2};" :: "r"(ah + off), "r"(h01), "r"(h23));
            asm volatile("st.shared.v2.b32 [%0], {%1,%2};" :: "r"(al + off), "r"(l01), "r"(l23));
        }
    };

    float acc[2][8][4];
    #pragma unroll
    for (int m = 0; m < 2; m++)
        #pragma unroll
        for (int n = 0; n < 8; n++)
            #pragma unroll
            for (int j = 0; j < 4; j++) acc[m][n][j] = 0.f;

    // per-lane ldmatrix address components
    const uint32_t a_base = sb + OFF_A + (uint32_t)((mp * 32 + (lane & 15)) * 128);
    const uint32_t axor = (uint32_t)((lane & 7) << 4);
    const uint32_t ak16 = (uint32_t)((lane >> 4) << 4);
    const int bq = lane >> 3;
    const uint32_t bn = (uint32_t)(((bq >> 1) << 3) + (lane & 7));
    const uint32_t bkb = (uint32_t)((bq & 1) * 16);
    const uint32_t bxor = (uint32_t)((lane & 7) << 4);

    stageX(0, 0); stageW(0, 0); cp_commit();

    for (int c = 0; c < NCH; c++) {
        __syncthreads();                       // prior iter's smem reads done
        if (c + 1 < NCH) { stageX(c + 1, (c + 1) & 1); stageW(c + 1, (c + 1) & 1);
                           cp_commit(); cp_wait1(); }
        else             { cp_wait0(); }
        __syncthreads();                       // chunk c landed
        convert(c & 1);
        __syncthreads();                       // A tiles ready

        const uint32_t wbase = sb + OFF_W + (c & 1) * 16384;
        #pragma unroll
        for (int kk = 0; kk < 2; kk++) {
            const uint32_t koff = (uint32_t)((kg * 2 + kk) * 32);
            uint32_t bh[16], bl[16];
            #pragma unroll
            for (int g = 0; g < 4; g++) {
                uint32_t ba = wbase + (g * 16 + bn) * 128 + ((koff + bkb) ^ bxor);
                ldsm4(bh[g*4], bh[g*4+1], bh[g*4+2], bh[g*4+3], ba);
                ldsm4(bl[g*4], bl[g*4+1], bl[g*4+2], bl[g*4+3], ba + 8192);
            }
            #pragma unroll
            for (int mt = 0; mt < 2; mt++) {
                uint32_t aa = a_base + (uint32_t)(mt * 2048) + ((koff + ak16) ^ axor);
                uint32_t ah[4], al[4];
                ldsm4(ah[0], ah[1], ah[2], ah[3], aa);
                ldsm4(al[0], al[1], al[2], al[3], aa + 16384);
                #pragma unroll
                for (int nt = 0; nt < 8; nt++) {
                    const int bi = (nt >> 1) * 4 + (nt & 1) * 2;
                    mma_bf16(acc[mt][nt], ah, bh[bi], bh[bi+1]);
                    mma_bf16(acc[mt][nt], ah, bl[bi], bl[bi+1]);
                    mma_bf16(acc[mt][nt], al, bh[bi], bh[bi+1]);
                }
            }
        }
    }

    // ---- epilogue: dump split-K partials, reduce, softmax + top-8 ----
    __syncthreads();
    float* slog = (float*)dsm;                 // [2][128][68], overlays X/A region
    #pragma unroll
    for (int mt = 0; mt < 2; mt++)
        #pragma unroll
        for (int nt = 0; nt < 8; nt++)
            #pragma unroll
            for (int j = 0; j < 4; j++) {
                int trow = mp * 32 + mt * 16 + (lane >> 2) + (j >> 1) * 8;
                int e = nt * 8 + (lane & 3) * 2 + (j & 1);
                slog[(kg * 128 + trow) * 68 + e] = acc[mt][nt][j];
            }
    __syncthreads();

    if (tid < TOKB) {
        const float* rb = (const float*)(dsm + OFF_RB);
        const int t = tb + tid;
        float l[N_EXP];
        #pragma unroll
        for (int e = 0; e < N_EXP; e++)
            l[e] = slog[tid * 68 + e] + slog[(128 + tid) * 68 + e] + rb[e];
        float mx = -1e30f;
        #pragma unroll
        for (int e = 0; e < N_EXP; e++) mx = fmaxf(mx, l[e]);
        float sum = 0.f;
        #pragma unroll
        for (int e = 0; e < N_EXP; e++) { float p = __expf(l[e] - mx); l[e] = p; sum += p; }
        const float inv = 1.0f / sum;
        unsigned long long mask = 0ull;
        float sw = 0.f;
        #pragma unroll
        for (int k = 0; k < TOPK; k++) {
            float best = -1.f; int bi = 0;
            #pragma unroll
            for (int e = 0; e < N_EXP; e++) {
                bool ok = !((mask >> e) & 1ull) && (l[e] > best);
                if (ok) { best = l[e]; bi = e; }
            }
            mask |= 1ull << bi;
            float w = best * inv;
            g_topw[t * TOPK + k]   = w;
            g_topidx[t * TOPK + k] = bi;
            sw += w;
        }
        g_sumw[t] = sw;
    }
}

// ================= Kernel B: dispatch/combine (unchanged, passing) =================
static constexpr int TBB = 128;
static constexpr int HCB = 128;

__global__ __launch_bounds__(256)
void combine_kernel(const float* __restrict__ X,
                    const float* __restrict__ EB,
                    float* __restrict__ OUT)
{
    __shared__ __align__(16) float bs[N_EXP * HCB];
    __shared__ float s_w[TBB * TOPK];
    __shared__ int   s_i[TBB * TOPK];
    __shared__ float s_s[TBB];

    const int tid = threadIdx.x;
    const int hb  = blockIdx.x * HCB;
    const int tb0 = blockIdx.y * TBB;

    #pragma unroll
    for (int r = 0; r < 8; r++) {
        int idx = tid + r * 256;
        int e = idx >> 5, c = idx & 31;
        *(float4*)&bs[e * HCB + c * 4] =
            *(const float4*)&EB[(size_t)e * H_DIM + hb + c * 4];
    }
    #pragma unroll
    for (int r = 0; r < 4; r++) {
        int idx = tid + r * 256;
        s_w[idx] = g_topw[tb0 * TOPK + idx];
        s_i[idx] = g_topidx[tb0 * TOPK + idx];
    }
    if (tid < TBB) s_s[tid] = g_sumw[tb0 + tid];
    __syncthreads();

    const int tl = tid >> 5;
    const int c  = tid & 31;

    float4 xv = *(const float4*)&X[(size_t)(tb0 + tl) * H_DIM + hb + c * 4];
    #pragma unroll 4
    for (int it = 0; it < TBB / 8; it++) {
        const int tt = tl + it * 8;
        float4 xn = xv;
        if (it + 1 < TBB / 8)
            xn = *(const float4*)&X[(size_t)(tb0 + tt + 8) * H_DIM + hb + c * 4];

        const float sw = s_s[tt];
        float4 a;
        a.x = xv.x * sw; a.y = xv.y * sw; a.z = xv.z * sw; a.w = xv.w * sw;
        #pragma unroll
        for (int k = 0; k < TOPK; k++) {
            const float wk = s_w[tt * TOPK + k];
            const int   ek = s_i[tt * TOPK + k];
            const float4 bv = *(const float4*)&bs[ek * HCB + c * 4];
            a.x += wk * bv.x; a.y += wk * bv.y; a.z += wk * bv.z; a.w += wk * bv.w;
        }
        *(float4*)&OUT[(size_t)(tb0 + tt) * H_DIM + hb + c * 4] = a;
        xv = xn;
    }
}

// ================= launch =================
extern "C" void kernel_launch(void* const* d_in, const int* in_sizes, int n_in,
                              void* d_out, int out_size) {
    const float* X  = (const float*)d_in[0];   // hidden_states [4,4096,2048]
    const float* RW = (const float*)d_in[1];   // router_weight [64,2048]
    const float* RB = (const float*)d_in[2];   // router_bias   [64]
    const float* EB = (const float*)d_in[3];   // expert_bias   [64,2048]
    float* OUT = (float*)d_out;

    cudaFuncSetAttribute(router_mma_kernel,
                         cudaFuncAttributeMaxDynamicSharedMemorySize, SMEM_R);

    wconvert_kernel<<<128, 256>>>(RW);
    router_mma_kernel<<<T_TOK / TOKB, 256, SMEM_R>>>(X, RB);
    dim3 gb(H_DIM / HCB, T_TOK / TBB);
    combine_kernel<<<gb, 256>>>(X, EB, OUT);
}

// round 5
// speedup vs baseline: 1.6637x; 1.2013x over previous
#include <cuda_runtime.h>
#include <cuda_bf16.h>
#include <cstdint>
#include <cstddef>

#define T_TOK 16384
#define H_DIM 2048
#define N_EXP 64
#define TOPK  8

// ---------------- scratch (no allocations allowed) ----------------
__device__ float g_topw[T_TOK * TOPK];
__device__ int   g_topidx[T_TOK * TOPK];
__device__ float g_sumw[T_TOK];
__device__ __nv_bfloat16 g_whi[N_EXP * H_DIM];
__device__ __nv_bfloat16 g_wlo[N_EXP * H_DIM];

// ---------------- helpers ----------------
__device__ __forceinline__ void cp_async16(uint32_t saddr, const void* gptr) {
    asm volatile("cp.async.cg.shared.global [%0], [%1], 16;" :: "r"(saddr), "l"(gptr));
}
__device__ __forceinline__ void cp_commit() { asm volatile("cp.async.commit_group;"); }
__device__ __forceinline__ void cp_wait1()  { asm volatile("cp.async.wait_group 1;"); }
__device__ __forceinline__ void cp_wait0()  { asm volatile("cp.async.wait_group 0;"); }

__device__ __forceinline__ void ldsm4(uint32_t& r0, uint32_t& r1, uint32_t& r2, uint32_t& r3,
                                      uint32_t addr) {
    asm volatile("ldmatrix.sync.aligned.m8n8.x4.shared.b16 {%0,%1,%2,%3}, [%4];"
                 : "=r"(r0), "=r"(r1), "=r"(r2), "=r"(r3) : "r"(addr));
}
__device__ __forceinline__ void mma_bf16(float* d, const uint32_t* a, uint32_t b0, uint32_t b1) {
    asm volatile("mma.sync.aligned.m16n8k16.row.col.f32.bf16.bf16.f32 "
                 "{%0,%1,%2,%3},{%4,%5,%6,%7},{%8,%9},{%0,%1,%2,%3};"
                 : "+f"(d[0]), "+f"(d[1]), "+f"(d[2]), "+f"(d[3])
                 : "r"(a[0]), "r"(a[1]), "r"(a[2]), "r"(a[3]), "r"(b0), "r"(b1));
}

// ================= Kernel W-convert: RW fp32 -> bf16 hi/lo =================
__global__ __launch_bounds__(256)
void wconvert_kernel(const float* __restrict__ RW) {
    int i = blockIdx.x * 256 + threadIdx.x;
    if (i < N_EXP * H_DIM) {
        float x = RW[i];
        __nv_bfloat16 hi = __float2bfloat16(x);
        g_whi[i] = hi;
        g_wlo[i] = __float2bfloat16(x - __bfloat162float(hi));
    }
}

// ================= Kernel A: HMMA router (bf16 hi/lo x3), pipelined =================
// CTA: 256 threads (8 warps), 128 tokens x 64 experts, K in 32 chunks of 64.
// Split-K: warps 0-3 handle k-steps 0-1, warps 4-7 steps 2-3.
static constexpr int TOKB = 128;
static constexpr int KC   = 64;
static constexpr int NCH  = H_DIM / KC;   // 32

static constexpr int OFF_X  = 0;          // 2 x 32768 fp32 X (XOR-swizzled 16B chunks)
static constexpr int OFF_A  = 65536;      // 2 x (Ahi 16384 + Alo 16384)
static constexpr int OFF_W  = 131072;     // 3 x (Whi 8192 + Wlo 8192)
static constexpr int OFF_RB = 180224;     // 256 B
static constexpr int SMEM_R = 180480;

__global__ __launch_bounds__(256, 1)
void router_mma_kernel(const float* __restrict__ X,
                       const float* __restrict__ RB)
{
    extern __shared__ __align__(16) char dsm[];
    const uint32_t sb = (uint32_t)__cvta_generic_to_shared(dsm);
    const int tid  = threadIdx.x;
    const int lane = tid & 31;
    const int wid  = tid >> 5;
    const int tb   = blockIdx.x * TOKB;
    const int kg   = wid >> 2;   // k-group
    const int mp   = wid & 3;    // token part

    if (tid < N_EXP) ((float*)(dsm + OFF_RB))[tid] = RB[tid];

    auto stageX = [&](int c, int b) {
        uint32_t dst = sb + OFF_X + b * 32768;
        const float* src = X + (size_t)tb * H_DIM + c * KC;
        #pragma unroll
        for (int r = 0; r < 8; r++) {
            int idx = tid + r * 256;            // 0..2047 16B chunks
            int row = idx >> 4, c16 = idx & 15;
            cp_async16(dst + (uint32_t)(row * 256 + ((c16 ^ (row & 7)) << 4)),
                       src + (size_t)row * H_DIM + c16 * 4);
        }
    };
    auto stageW = [&](int c, int b) {
        uint32_t wh = sb + OFF_W + b * 16384;
        const __nv_bfloat16* sh = g_whi + c * KC;
        const __nv_bfloat16* sl = g_wlo + c * KC;
        #pragma unroll
        for (int r = 0; r < 2; r++) {
            int idx = tid + r * 256;            // 0..511 16B chunks
            int row = idx >> 3, c16 = idx & 7;
            uint32_t so = (uint32_t)(row * 128 + ((c16 ^ (row & 7)) << 4));
            cp_async16(wh + so,        sh + (size_t)row * H_DIM + c16 * 8);
            cp_async16(wh + 8192 + so, sl + (size_t)row * H_DIM + c16 * 8);
        }
    };
    // convert: STRICTLY self-staged (same idx mapping as stageX) so each thread
    // only reads bytes its own cp.async wrote (wait_group gives visibility).
    auto convert = [&](int b) {
        uint32_t xb = sb + OFF_X + b * 32768;
        uint32_t ab = sb + OFF_A + b * 32768;
        #pragma unroll
        for (int r = 0; r < 8; r++) {
            int idx = tid + r * 256;
            int row = idx >> 4, c16 = idx & 15;
            int rx = row & 7;
            float4 f;
            asm volatile("ld.shared.v4.f32 {%0,%1,%2,%3}, [%4];"
                         : "=f"(f.x), "=f"(f.y), "=f"(f.z), "=f"(f.w)
                         : "r"(xb + (uint32_t)(row * 256 + ((c16 ^ rx) << 4))));
            uint32_t h01, h23, l01, l23;
            asm("cvt.rn.bf16x2.f32 %0, %1, %2;" : "=r"(h01) : "f"(f.y), "f"(f.x));
            asm("cvt.rn.bf16x2.f32 %0, %1, %2;" : "=r"(h23) : "f"(f.w), "f"(f.z));
            float e0 = f.x - __uint_as_float(h01 << 16);
            float e1 = f.y - __uint_as_float(h01 & 0xffff0000u);
            float e2 = f.z - __uint_as_float(h23 << 16);
            float e3 = f.w - __uint_as_float(h23 & 0xffff0000u);
            asm("cvt.rn.bf16x2.f32 %0, %1, %2;" : "=r"(l01) : "f"(e1), "f"(e0));
            asm("cvt.rn.bf16x2.f32 %0, %1, %2;" : "=r"(l23) : "f"(e3), "f"(e2));
            uint32_t off = (uint32_t)(row * 128 + (((c16 >> 1) ^ rx) << 4) + (c16 & 1) * 8);
            asm volatile("st.shared.v2.b32 [%0], {%1,%2};" :: "r"(ab + off), "r"(h01), "r"(h23));
            asm volatile("st.shared.v2.b32 [%0], {%1,%2};" :: "r"(ab + 16384 + off), "r"(l01), "r"(l23));
        }
    };

    float acc[2][8][4];
    #pragma unroll
    for (int m = 0; m < 2; m++)
        #pragma unroll
        for (int n = 0; n < 8; n++)
            #pragma unroll
            for (int j = 0; j < 4; j++) acc[m][n][j] = 0.f;

    const uint32_t a_roff = (uint32_t)((mp * 32 + (lane & 15)) * 128);
    const uint32_t axor = (uint32_t)((lane & 7) << 4);
    const uint32_t ak16 = (uint32_t)((lane >> 4) << 4);
    const int bq = lane >> 3;
    const uint32_t bn = (uint32_t)(((bq >> 1) << 3) + (lane & 7));
    const uint32_t bkb = (uint32_t)((bq & 1) * 16);
    const uint32_t bxor = (uint32_t)((lane & 7) << 4);

    // prologue: stage chunks 0,1; convert chunk 0
    stageX(0, 0); stageW(0, 0); cp_commit();
    stageX(1, 1); stageW(1, 1); cp_commit();
    cp_wait1();                 // group0 done (own copies visible)
    convert(0);
    __syncthreads();            // A(0), W(0) visible to all warps

    for (int c = 0; c < NCH; c++) {
        if (c + 2 < NCH) { stageX(c + 2, c & 1); stageW(c + 2, (c + 2) % 3); cp_commit(); }

        // ---- MMA(c) on A[c&1], W[c%3] ----
        const uint32_t wbase = sb + OFF_W + (uint32_t)((c % 3) * 16384);
        const uint32_t abuf  = sb + OFF_A + (uint32_t)((c & 1) * 32768);
        #pragma unroll
        for (int kk = 0; kk < 2; kk++) {
            const uint32_t koff = (uint32_t)((kg * 2 + kk) * 32);
            uint32_t bh[16], bl[16];
            #pragma unroll
            for (int g = 0; g < 4; g++) {
                uint32_t ba = wbase + (g * 16 + bn) * 128 + ((koff + bkb) ^ bxor);
                ldsm4(bh[g*4], bh[g*4+1], bh[g*4+2], bh[g*4+3], ba);
                ldsm4(bl[g*4], bl[g*4+1], bl[g*4+2], bl[g*4+3], ba + 8192);
            }
            #pragma unroll
            for (int mt = 0; mt < 2; mt++) {
                uint32_t aa = abuf + a_roff + (uint32_t)(mt * 2048) + ((koff + ak16) ^ axor);
                uint32_t ah[4], al[4];
                ldsm4(ah[0], ah[1], ah[2], ah[3], aa);
                ldsm4(al[0], al[1], al[2], al[3], aa + 16384);
                #pragma unroll
                for (int nt = 0; nt < 8; nt++) {
                    const int bi = (nt >> 1) * 4 + (nt & 1) * 2;
                    mma_bf16(acc[mt][nt], ah, bh[bi], bh[bi+1]);
                    mma_bf16(acc[mt][nt], ah, bl[bi], bl[bi+1]);
                    mma_bf16(acc[mt][nt], al, bh[bi], bh[bi+1]);
                }
            }
        }

        // ---- convert(c+1) overlapped under MMA issue ----
        if (c + 1 < NCH) {
            if (c + 2 < NCH) cp_wait1(); else cp_wait0();
            convert((c + 1) & 1);
        }
        __syncthreads();
    }

    // ---- epilogue: dump split-K partials, reduce, softmax + top-8 ----
    float* slog = (float*)dsm;                 // [2][128][68] overlays X/A region
    #pragma unroll
    for (int mt = 0; mt < 2; mt++)
        #pragma unroll
        for (int nt = 0; nt < 8; nt++)
            #pragma unroll
            for (int j = 0; j < 4; j++) {
                int trow = mp * 32 + mt * 16 + (lane >> 2) + (j >> 1) * 8;
                int e = nt * 8 + (lane & 3) * 2 + (j & 1);
                slog[(kg * 128 + trow) * 68 + e] = acc[mt][nt][j];
            }
    __syncthreads();

    if (tid < TOKB) {
        const float* rb = (const float*)(dsm + OFF_RB);
        const int t = tb + tid;
        float l[N_EXP];
        #pragma unroll
        for (int e = 0; e < N_EXP; e++)
            l[e] = slog[tid * 68 + e] + slog[(128 + tid) * 68 + e] + rb[e];
        float mx = -1e30f;
        #pragma unroll
        for (int e = 0; e < N_EXP; e++) mx = fmaxf(mx, l[e]);
        float sum = 0.f;
        #pragma unroll
        for (int e = 0; e < N_EXP; e++) { float p = __expf(l[e] - mx); l[e] = p; sum += p; }
        const float inv = 1.0f / sum;
        unsigned long long mask = 0ull;
        float sw = 0.f;
        #pragma unroll
        for (int k = 0; k < TOPK; k++) {
            float best = -1.f; int bi = 0;
            #pragma unroll
            for (int e = 0; e < N_EXP; e++) {
                bool ok = !((mask >> e) & 1ull) && (l[e] > best);
                if (ok) { best = l[e]; bi = e; }
            }
            mask |= 1ull << bi;
            float w = best * inv;
            g_topw[t * TOPK + k]   = w;
            g_topidx[t * TOPK + k] = bi;
            sw += w;
        }
        g_sumw[t] = sw;
    }
}

// ================= Kernel B: dispatch/combine (bf16 bias + packed meta) =================
static constexpr int TBB = 128;
static constexpr int HCB = 128;

__global__ __launch_bounds__(256)
void combine_kernel(const float* __restrict__ X,
                    const float* __restrict__ EB,
                    float* __restrict__ OUT)
{
    __shared__ __align__(16) uint32_t bs[N_EXP * 64];   // bf16x2, 16 KB
    __shared__ __align__(16) float4 s_meta[TBB * 3];    // 6 KB: w0-3 | w4-7 | {sumw, idx03, idx47, -}

    const int tid = threadIdx.x;
    const int hb  = blockIdx.x * HCB;
    const int tb0 = blockIdx.y * TBB;

    // stage bias slice as bf16x2 (64 experts x 128 floats -> 64 x 64 uint32)
    #pragma unroll
    for (int r = 0; r < 8; r++) {
        int idx = tid + r * 256;          // 0..2047 float4 chunks
        int e = idx >> 5, c = idx & 31;
        float4 f = *(const float4*)&EB[(size_t)e * H_DIM + hb + c * 4];
        uint32_t p0, p1;
        asm("cvt.rn.bf16x2.f32 %0, %1, %2;" : "=r"(p0) : "f"(f.y), "f"(f.x));
        asm("cvt.rn.bf16x2.f32 %0, %1, %2;" : "=r"(p1) : "f"(f.w), "f"(f.z));
        *(uint2*)&bs[e * 64 + c * 2] = make_uint2(p0, p1);
    }
    // stage packed per-token metadata
    if (tid < TBB) {
        const int t = tb0 + tid;
        float4 w0 = *(const float4*)&g_topw[t * TOPK];
        float4 w1 = *(const float4*)&g_topw[t * TOPK + 4];
        int4 i0 = *(const int4*)&g_topidx[t * TOPK];
        int4 i1 = *(const int4*)&g_topidx[t * TOPK + 4];
        uint32_t p03 = (uint32_t)i0.x | ((uint32_t)i0.y << 8) |
                       ((uint32_t)i0.z << 16) | ((uint32_t)i0.w << 24);
        uint32_t p47 = (uint32_t)i1.x | ((uint32_t)i1.y << 8) |
                       ((uint32_t)i1.z << 16) | ((uint32_t)i1.w << 24);
        s_meta[tid * 3 + 0] = w0;
        s_meta[tid * 3 + 1] = w1;
        s_meta[tid * 3 + 2] = make_float4(g_sumw[t], __uint_as_float(p03),
                                          __uint_as_float(p47), 0.f);
    }
    __syncthreads();

    const int tl = tid >> 5;
    const int c  = tid & 31;

    float4 xv = *(const float4*)&X[(size_t)(tb0 + tl) * H_DIM + hb + c * 4];
    #pragma unroll 4
    for (int it = 0; it < TBB / 8; it++) {
        const int tt = tl + it * 8;
        float4 xn = xv;
        if (it + 1 < TBB / 8)
            xn = *(const float4*)&X[(size_t)(tb0 + tt + 8) * H_DIM + hb + c * 4];

        const float4 m0 = s_meta[tt * 3 + 0];
        const float4 m1 = s_meta[tt * 3 + 1];
        const float4 m2 = s_meta[tt * 3 + 2];
        const uint32_t i03 = __float_as_uint(m2.y);
        const uint32_t i47 = __float_as_uint(m2.z);
        const float wk[8] = {m0.x, m0.y, m0.z, m0.w, m1.x, m1.y, m1.z, m1.w};

        const float sw = m2.x;
        float4 a;
        a.x = xv.x * sw; a.y = xv.y * sw; a.z = xv.z * sw; a.w = xv.w * sw;
        #pragma unroll
        for (int k = 0; k < TOPK; k++) {
            const uint32_t ek = ((k < 4 ? (i03 >> (k * 8)) : (i47 >> ((k - 4) * 8))) & 0xffu);
            const uint2 b2 = *(const uint2*)&bs[ek * 64 + c * 2];
            a.x += wk[k] * __uint_as_float(b2.x << 16);
            a.y += wk[k] * __uint_as_float(b2.x & 0xffff0000u);
            a.z += wk[k] * __uint_as_float(b2.y << 16);
            a.w += wk[k] * __uint_as_float(b2.y & 0xffff0000u);
        }
        *(float4*)&OUT[(size_t)(tb0 + tt) * H_DIM + hb + c * 4] = a;
        xv = xn;
    }
}

// ================= launch =================
extern "C" void kernel_launch(void* const* d_in, const int* in_sizes, int n_in,
                              void* d_out, int out_size) {
    const float* X  = (const float*)d_in[0];   // hidden_states [4,4096,2048]
    const float* RW = (const float*)d_in[1];   // router_weight [64,2048]
    const float* RB = (const float*)d_in[2];   // router_bias   [64]
    const float* EB = (const float*)d_in[3];   // expert_bias   [64,2048]
    float* OUT = (float*)d_out;

    cudaFuncSetAttribute(router_mma_kernel,
                         cudaFuncAttributeMaxDynamicSharedMemorySize, SMEM_R);

    wconvert_kernel<<<512, 256>>>(RW);
    router_mma_kernel<<<T_TOK / TOKB, 256, SMEM_R>>>(X, RB);
    dim3 gb(H_DIM / HCB, T_TOK / TBB);
    combine_kernel<<<gb, 256>>>(X, EB, OUT);
}

// round 7
// speedup vs baseline: 1.7636x; 1.0600x over previous
#include <cuda_runtime.h>
#include <cuda_bf16.h>
#include <cstdint>
#include <cstddef>

#define T_TOK 16384
#define H_DIM 2048
#define N_EXP 64
#define TOPK  8

// ---------------- scratch (no allocations allowed) ----------------
__device__ float g_topw[T_TOK * TOPK];
__device__ int   g_topidx[T_TOK * TOPK];
__device__ float g_sumw[T_TOK];
__device__ __nv_bfloat16 g_whi[N_EXP * H_DIM];
__device__ __nv_bfloat16 g_wlo[N_EXP * H_DIM];

// ---------------- helpers ----------------
__device__ __forceinline__ void cp_async16(uint32_t saddr, const void* gptr) {
    asm volatile("cp.async.cg.shared.global [%0], [%1], 16;" :: "r"(saddr), "l"(gptr));
}
__device__ __forceinline__ void cp_commit() { asm volatile("cp.async.commit_group;"); }
__device__ __forceinline__ void cp_wait1()  { asm volatile("cp.async.wait_group 1;"); }
__device__ __forceinline__ void cp_wait0()  { asm volatile("cp.async.wait_group 0;"); }

__device__ __forceinline__ void ldsm4(uint32_t& r0, uint32_t& r1, uint32_t& r2, uint32_t& r3,
                                      uint32_t addr) {
    asm volatile("ldmatrix.sync.aligned.m8n8.x4.shared.b16 {%0,%1,%2,%3}, [%4];"
                 : "=r"(r0), "=r"(r1), "=r"(r2), "=r"(r3) : "r"(addr));
}
__device__ __forceinline__ void mma_bf16(float* d, const uint32_t* a, uint32_t b0, uint32_t b1) {
    asm volatile("mma.sync.aligned.m16n8k16.row.col.f32.bf16.bf16.f32 "
                 "{%0,%1,%2,%3},{%4,%5,%6,%7},{%8,%9},{%0,%1,%2,%3};"
                 : "+f"(d[0]), "+f"(d[1]), "+f"(d[2]), "+f"(d[3])
                 : "r"(a[0]), "r"(a[1]), "r"(a[2]), "r"(a[3]), "r"(b0), "r"(b1));
}

// ================= Kernel W-convert: RW fp32 -> bf16 hi/lo (vectorized) =================
__global__ __launch_bounds__(256)
void wconvert_kernel(const float* __restrict__ RW) {
    int i4 = blockIdx.x * 256 + threadIdx.x;          // 32768 float4 slots
    if (i4 < (N_EXP * H_DIM) / 4) {
        float4 f = *(const float4*)&RW[i4 * 4];
        float h0 = __bfloat162float(__float2bfloat16(f.x));
        float h1 = __bfloat162float(__float2bfloat16(f.y));
        float h2 = __bfloat162float(__float2bfloat16(f.z));
        float h3 = __bfloat162float(__float2bfloat16(f.w));
        __nv_bfloat162 hA = {__float2bfloat16(h0), __float2bfloat16(h1)};
        __nv_bfloat162 hB = {__float2bfloat16(h2), __float2bfloat16(h3)};
        __nv_bfloat162 lA = {__float2bfloat16(f.x - h0), __float2bfloat16(f.y - h1)};
        __nv_bfloat162 lB = {__float2bfloat16(f.z - h2), __float2bfloat16(f.w - h3)};
        *(uint2*)&g_whi[i4 * 4] = make_uint2(*(uint32_t*)&hA, *(uint32_t*)&hB);
        *(uint2*)&g_wlo[i4 * 4] = make_uint2(*(uint32_t*)&lA, *(uint32_t*)&lB);
    }
}

// ================= Kernel A: HMMA router (bf16 hi/lo x3), LDG-convert =================
// CTA: 256 threads (8 warps), 128 tokens x 64 experts, K in 32 chunks of 64.
// Warp layout: mp in {0,1} -> 64 tokens (4 m16 tiles); kg in {0..3} -> one k16 step.
static constexpr int TOKB = 128;
static constexpr int KC   = 64;
static constexpr int NCH  = H_DIM / KC;   // 32

static constexpr int OFF_A  = 0;          // 2 x (Ahi 16384 + Alo 16384) = 65536
static constexpr int OFF_W  = 65536;      // 3 x (Whi 8192 + Wlo 8192)  = 49152
static constexpr int OFF_RB = 139264;     // AFTER the slog overlay (4*128*68*4 = 139264)
static constexpr int SMEM_R = 139520;

__global__ __launch_bounds__(256, 1)
void router_mma_kernel(const float* __restrict__ X,
                       const float* __restrict__ RB)
{
    extern __shared__ __align__(16) char dsm[];
    const uint32_t sb = (uint32_t)__cvta_generic_to_shared(dsm);
    const int tid  = threadIdx.x;
    const int lane = tid & 31;
    const int wid  = tid >> 5;
    const int tb   = blockIdx.x * TOKB;
    const int kg   = wid & 3;    // k16 step within 64-k chunk
    const int mp   = wid >> 2;   // token half: tokens [mp*64, mp*64+64)

    if (tid < N_EXP) ((float*)(dsm + OFF_RB))[tid] = RB[tid];

    auto stageW = [&](int c, int b) {
        uint32_t wh = sb + OFF_W + b * 16384;
        const __nv_bfloat16* sh = g_whi + c * KC;
        const __nv_bfloat16* sl = g_wlo + c * KC;
        #pragma unroll
        for (int r = 0; r < 2; r++) {
            int idx = tid + r * 256;            // 0..511 16B chunks
            int row = idx >> 3, c16 = idx & 7;
            uint32_t so = (uint32_t)(row * 128 + ((c16 ^ (row & 7)) << 4));
            cp_async16(wh + so,        sh + (size_t)row * H_DIM + c16 * 8);
            cp_async16(wh + 8192 + so, sl + (size_t)row * H_DIM + c16 * 8);
        }
    };

    float4 xr[8];   // prefetched X chunk (128 rows x 64 cols / 256 thr = 8 float4)
    auto ldgX = [&](int c) {
        const float* src = X + (size_t)tb * H_DIM + c * KC;
        #pragma unroll
        for (int r = 0; r < 8; r++) {
            int idx = tid + r * 256;
            int row = idx >> 4, c16 = idx & 15;
            xr[r] = *(const float4*)(src + (size_t)row * H_DIM + c16 * 4);
        }
    };
    // convert xr -> bf16 hi/lo tiles in A buffer b (XOR-swizzled rows of 128B)
    auto convertReg = [&](int b) {
        uint32_t ab = sb + OFF_A + (uint32_t)(b * 32768);
        #pragma unroll
        for (int r = 0; r < 8; r++) {
            int idx = tid + r * 256;
            int row = idx >> 4, c16 = idx & 15;
            int rx = row & 7;
            float4 f = xr[r];
            uint32_t h01, h23, l01, l23;
            asm("cvt.rn.bf16x2.f32 %0, %1, %2;" : "=r"(h01) : "f"(f.y), "f"(f.x));
            asm("cvt.rn.bf16x2.f32 %0, %1, %2;" : "=r"(h23) : "f"(f.w), "f"(f.z));
            float e0 = f.x - __uint_as_float(h01 << 16);
            float e1 = f.y - __uint_as_float(h01 & 0xffff0000u);
            float e2 = f.z - __uint_as_float(h23 << 16);
            float e3 = f.w - __uint_as_float(h23 & 0xffff0000u);
            asm("cvt.rn.bf16x2.f32 %0, %1, %2;" : "=r"(l01) : "f"(e1), "f"(e0));
            asm("cvt.rn.bf16x2.f32 %0, %1, %2;" : "=r"(l23) : "f"(e3), "f"(e2));
            uint32_t off = (uint32_t)(row * 128 + (((c16 >> 1) ^ rx) << 4) + (c16 & 1) * 8);
            asm volatile("st.shared.v2.b32 [%0], {%1,%2};" :: "r"(ab + off), "r"(h01), "r"(h23));
            asm volatile("st.shared.v2.b32 [%0], {%1,%2};" :: "r"(ab + 16384 + off), "r"(l01), "r"(l23));
        }
    };

    float acc[4][8][4];
    #pragma unroll
    for (int m = 0; m < 4; m++)
        #pragma unroll
        for (int n = 0; n < 8; n++)
            #pragma unroll
            for (int j = 0; j < 4; j++) acc[m][n][j] = 0.f;

    const uint32_t a_roff = (uint32_t)((mp * 64 + (lane & 15)) * 128);
    const uint32_t axor = (uint32_t)((lane & 7) << 4);
    const uint32_t ak16 = (uint32_t)((lane >> 4) << 4);
    const int bq = lane >> 3;
    const uint32_t bn = (uint32_t)(((bq >> 1) << 3) + (lane & 7));
    const uint32_t bkb = (uint32_t)((bq & 1) * 16);
    const uint32_t bxor = (uint32_t)((lane & 7) << 4);
    const uint32_t koff = (uint32_t)(kg * 32);    // one k16 step per warp

    // prologue
    stageW(0, 0); cp_commit();
    stageW(1, 1); cp_commit();
    ldgX(0);
    convertReg(0);
    ldgX(1);
    cp_wait1();                 // W(0) complete
    __syncthreads();            // A(0), W(0) visible

    for (int c = 0; c < NCH; c++) {
        if (c + 2 < NCH) { stageW(c + 2, (c + 2) % 3); cp_commit(); }

        // ---- MMA(c) on A[c&1], W[c%3] ----
        const uint32_t wbase = sb + OFF_W + (uint32_t)((c % 3) * 16384);
        const uint32_t abuf  = sb + OFF_A + (uint32_t)((c & 1) * 32768);
        uint32_t bh[16], bl[16];
        #pragma unroll
        for (int g = 0; g < 4; g++) {
            uint32_t ba = wbase + (g * 16 + bn) * 128 + ((koff + bkb) ^ bxor);
            ldsm4(bh[g*4], bh[g*4+1], bh[g*4+2], bh[g*4+3], ba);
            ldsm4(bl[g*4], bl[g*4+1], bl[g*4+2], bl[g*4+3], ba + 8192);
        }
        #pragma unroll
        for (int mt = 0; mt < 4; mt++) {
            uint32_t aa = abuf + a_roff + (uint32_t)(mt * 2048) + ((koff + ak16) ^ axor);
            uint32_t ah[4], al[4];
            ldsm4(ah[0], ah[1], ah[2], ah[3], aa);
            ldsm4(al[0], al[1], al[2], al[3], aa + 16384);
            #pragma unroll
            for (int nt = 0; nt < 8; nt++) {
                const int bi = (nt >> 1) * 4 + (nt & 1) * 2;
                mma_bf16(acc[mt][nt], ah, bh[bi], bh[bi+1]);
                mma_bf16(acc[mt][nt], ah, bl[bi], bl[bi+1]);
                mma_bf16(acc[mt][nt], al, bh[bi], bh[bi+1]);
            }
        }

        // ---- convert(c+1) from regs; prefetch LDG(c+2) ----
        if (c + 1 < NCH) convertReg((c + 1) & 1);
        if (c + 2 < NCH) { ldgX(c + 2); cp_wait1(); }
        else             { cp_wait0(); }
        __syncthreads();
    }

    // ---- epilogue: dump 4 split-K partials, reduce, softmax + top-8 ----
    float* slog = (float*)dsm;                 // [4][128][68] overlays A/W (NOT RB)
    #pragma unroll
    for (int mt = 0; mt < 4; mt++)
        #pragma unroll
        for (int nt = 0; nt < 8; nt++)
            #pragma unroll
            for (int j = 0; j < 4; j++) {
                int trow = mp * 64 + mt * 16 + (lane >> 2) + (j >> 1) * 8;
                int e = nt * 8 + (lane & 3) * 2 + (j & 1);
                slog[(kg * 128 + trow) * 68 + e] = acc[mt][nt][j];
            }
    __syncthreads();

    if (tid < TOKB) {
        const float* rb = (const float*)(dsm + OFF_RB);
        const int t = tb + tid;
        float l[N_EXP];
        #pragma unroll
        for (int e = 0; e < N_EXP; e++)
            l[e] = (slog[tid * 68 + e] + slog[(128 + tid) * 68 + e]) +
                   (slog[(256 + tid) * 68 + e] + slog[(384 + tid) * 68 + e]) + rb[e];
        float mx = -1e30f;
        #pragma unroll
        for (int e = 0; e < N_EXP; e++) mx = fmaxf(mx, l[e]);
        float sum = 0.f;
        #pragma unroll
        for (int e = 0; e < N_EXP; e++) { float p = __expf(l[e] - mx); l[e] = p; sum += p; }
        const float inv = 1.0f / sum;
        unsigned long long mask = 0ull;
        float sw = 0.f;
        #pragma unroll
        for (int k = 0; k < TOPK; k++) {
            float best = -1.f; int bi = 0;
            #pragma unroll
            for (int e = 0; e < N_EXP; e++) {
                bool ok = !((mask >> e) & 1ull) && (l[e] > best);
                if (ok) { best = l[e]; bi = e; }
            }
            mask |= 1ull << bi;
            float w = best * inv;
            g_topw[t * TOPK + k]   = w;
            g_topidx[t * TOPK + k] = bi;
            sw += w;
        }
        g_sumw[t] = sw;
    }
}

// ================= Kernel B: dispatch/combine (bf16 bias + packed meta) =================
static constexpr int TBB = 128;
static constexpr int HCB = 128;

__global__ __launch_bounds__(256)
void combine_kernel(const float* __restrict__ X,
                    const float* __restrict__ EB,
                    float* __restrict__ OUT)
{
    __shared__ __align__(16) uint32_t bs[N_EXP * 64];   // bf16x2, 16 KB
    __shared__ __align__(16) float4 s_meta[TBB * 3];    // w0-3 | w4-7 | {sumw, idx03, idx47, -}

    const int tid = threadIdx.x;
    const int hb  = blockIdx.x * HCB;
    const int tb0 = blockIdx.y * TBB;

    #pragma unroll
    for (int r = 0; r < 8; r++) {
        int idx = tid + r * 256;
        int e = idx >> 5, c = idx & 31;
        float4 f = *(const float4*)&EB[(size_t)e * H_DIM + hb + c * 4];
        uint32_t p0, p1;
        asm("cvt.rn.bf16x2.f32 %0, %1, %2;" : "=r"(p0) : "f"(f.y), "f"(f.x));
        asm("cvt.rn.bf16x2.f32 %0, %1, %2;" : "=r"(p1) : "f"(f.w), "f"(f.z));
        *(uint2*)&bs[e * 64 + c * 2] = make_uint2(p0, p1);
    }
    if (tid < TBB) {
        const int t = tb0 + tid;
        float4 w0 = *(const float4*)&g_topw[t * TOPK];
        float4 w1 = *(const float4*)&g_topw[t * TOPK + 4];
        int4 i0 = *(const int4*)&g_topidx[t * TOPK];
        int4 i1 = *(const int4*)&g_topidx[t * TOPK + 4];
        uint32_t p03 = (uint32_t)i0.x | ((uint32_t)i0.y << 8) |
                       ((uint32_t)i0.z << 16) | ((uint32_t)i0.w << 24);
        uint32_t p47 = (uint32_t)i1.x | ((uint32_t)i1.y << 8) |
                       ((uint32_t)i1.z << 16) | ((uint32_t)i1.w << 24);
        s_meta[tid * 3 + 0] = w0;
        s_meta[tid * 3 + 1] = w1;
        s_meta[tid * 3 + 2] = make_float4(g_sumw[t], __uint_as_float(p03),
                                          __uint_as_float(p47), 0.f);
    }
    __syncthreads();

    const int tl = tid >> 5;
    const int c  = tid & 31;

    float4 xv = *(const float4*)&X[(size_t)(tb0 + tl) * H_DIM + hb + c * 4];
    #pragma unroll 4
    for (int it = 0; it < TBB / 8; it++) {
        const int tt = tl + it * 8;
        float4 xn = xv;
        if (it + 1 < TBB / 8)
            xn = *(const float4*)&X[(size_t)(tb0 + tt + 8) * H_DIM + hb + c * 4];

        const float4 m0 = s_meta[tt * 3 + 0];
        const float4 m1 = s_meta[tt * 3 + 1];
        const float4 m2 = s_meta[tt * 3 + 2];
        const uint32_t i03 = __float_as_uint(m2.y);
        const uint32_t i47 = __float_as_uint(m2.z);
        const float wk[8] = {m0.x, m0.y, m0.z, m0.w, m1.x, m1.y, m1.z, m1.w};

        const float sw = m2.x;
        float4 a;
        a.x = xv.x * sw; a.y = xv.y * sw; a.z = xv.z * sw; a.w = xv.w * sw;
        #pragma unroll
        for (int k = 0; k < TOPK; k++) {
            const uint32_t ek = ((k < 4 ? (i03 >> (k * 8)) : (i47 >> ((k - 4) * 8))) & 0xffu);
            const uint2 b2 = *(const uint2*)&bs[ek * 64 + c * 2];
            a.x += wk[k] * __uint_as_float(b2.x << 16);
            a.y += wk[k] * __uint_as_float(b2.x & 0xffff0000u);
            a.z += wk[k] * __uint_as_float(b2.y << 16);
            a.w += wk[k] * __uint_as_float(b2.y & 0xffff0000u);
        }
        *(float4*)&OUT[(size_t)(tb0 + tt) * H_DIM + hb + c * 4] = a;
        xv = xn;
    }
}

// ================= launch =================
extern "C" void kernel_launch(void* const* d_in, const int* in_sizes, int n_in,
                              void* d_out, int out_size) {
    const float* X  = (const float*)d_in[0];   // hidden_states [4,4096,2048]
    const float* RW = (const float*)d_in[1];   // router_weight [64,2048]
    const float* RB = (const float*)d_in[2];   // router_bias   [64]
    const float* EB = (const float*)d_in[3];   // expert_bias   [64,2048]
    float* OUT = (float*)d_out;

    cudaFuncSetAttribute(router_mma_kernel,
                         cudaFuncAttributeMaxDynamicSharedMemorySize, SMEM_R);

    wconvert_kernel<<<(N_EXP * H_DIM / 4 + 255) / 256, 256>>>(RW);
    router_mma_kernel<<<T_TOK / TOKB, 256, SMEM_R>>>(X, RB);
    dim3 gb(H_DIM / HCB, T_TOK / TBB);
    combine_kernel<<<gb, 256>>>(X, EB, OUT);
}